// round 11
// baseline (speedup 1.0000x reference)
#include <cuda_runtime.h>
#include <cuda_fp16.h>
#include <cstdint>

#define NN 50000
#define EE 800000
#define SCAN_B 1024
#define NBLK ((NN + SCAN_B - 1) / SCAN_B)   // 49

// ---------------- scratch ----------------
__device__ __align__(16) int    g_hist[NN];        // zeroed at load; self-zeroing per replay
__device__ __align__(16) int    g_rowptr[NN + 1];
__device__ __align__(16) int    g_fill[NN];
__device__ __align__(16) int    g_prefix[NBLK];
__device__ __align__(16) int    g_ready[NBLK];     // zeroed at load; reader resets
__device__ __align__(16) float  g_dinv[NN];
__device__ __align__(16) int2   g_csr_sn[EE];              // {src, norm bits}
__device__ __align__(16) __half g_h1h[(size_t)NN * 128];   // fp16 layer-1 linear out
__device__ __align__(16) __half g_x2h[(size_t)NN * 128];   // fp16 relu(layer1)
__device__ __align__(16) __half g_h2h[(size_t)NN * 64];    // fp16 layer-2 linear out

// ---------------- side stream + events (static init) ----------------
struct SideStream {
    cudaStream_t s;
    cudaEvent_t evFork, evJoin;
    SideStream() {
        cudaStreamCreateWithFlags(&s, cudaStreamNonBlocking);
        cudaEventCreateWithFlags(&evFork, cudaEventDisableTiming);
        cudaEventCreateWithFlags(&evJoin, cudaEventDisableTiming);
    }
};
static SideStream g_ss;

// ---------------- packed fp32 helpers ----------------
__device__ __forceinline__ unsigned long long dup_f32x2(float v) {
    unsigned long long r;
    asm("mov.b64 %0, {%1, %1};" : "=l"(r) : "f"(v));
    return r;
}
__device__ __forceinline__ void ffma2(unsigned long long& acc,
                                      unsigned long long a, unsigned long long b) {
    asm("fma.rn.f32x2 %0, %1, %2, %0;" : "+l"(acc) : "l"(a), "l"(b));
}
__device__ __forceinline__ void unpack2(unsigned long long v, float& lo, float& hi) {
    asm("mov.b64 {%0, %1}, %2;" : "=f"(lo), "=f"(hi) : "l"(v));
}

union H8U  { uint4 u; __half2 h[4]; };
union H4U  { uint2 u; __half2 h[2]; };

// ---------------- edge decode + degree histogram ----------------
__global__ void prep_edges(const void* __restrict__ ei, int* __restrict__ hist,
                           int nE, int n) {
    int e = blockIdx.x * blockDim.x + threadIdx.x;
    if (e >= nE) return;
    const int* w = (const int*)ei;
    bool is64 = (w[1] == 0) & (w[3] == 0) & (w[5] == 0) & (w[7] == 0);
    int d;
    if (is64) d = (int)((const long long*)ei)[nE + e];
    else      d = w[nE + e];
    d = min(max(d, 0), n - 1);
    atomicAdd(&hist[d], 1);
}

// ---------------- chained scan: one kernel, 49 resident blocks ----------------
__global__ void scan_chain(int* __restrict__ hist, int* __restrict__ rowptr,
                           int* __restrict__ fill, float* __restrict__ dinv,
                           int* __restrict__ prefix, int* __restrict__ ready,
                           int n, int nblk) {
    __shared__ int warpsum[32];
    __shared__ int s_total, s_prev;
    int b = blockIdx.x;
    int t = threadIdx.x, lane = t & 31, wid = t >> 5;
    int idx = b * SCAN_B + t;
    int v = (idx < n) ? hist[idx] : 0;
    if (idx < n) {
        dinv[idx] = rsqrtf(1.0f + (float)v);
        hist[idx] = 0;   // self-zero for next graph replay
    }
    int x = v;
#pragma unroll
    for (int off = 1; off < 32; off <<= 1) {
        int y = __shfl_up_sync(0xffffffff, x, off);
        if (lane >= off) x += y;
    }
    if (lane == 31) warpsum[wid] = x;
    __syncthreads();
    if (wid == 0) {
        int s = warpsum[lane];
#pragma unroll
        for (int off = 1; off < 32; off <<= 1) {
            int y = __shfl_up_sync(0xffffffff, s, off);
            if (lane >= off) s += y;
        }
        warpsum[lane] = s;
    }
    __syncthreads();
    int warpoff = (wid > 0) ? warpsum[wid - 1] : 0;
    int incl = x + warpoff;
    if (t == SCAN_B - 1) s_total = incl;
    __syncthreads();

    if (t == 0) {
        int prev = 0;
        if (b > 0) {
            volatile int* r = ready;
            while (r[b - 1] == 0) { }
            __threadfence();
            prev = prefix[b - 1];
            r[b - 1] = 0;   // reader resets for next replay
        }
        s_prev = prev;
        if (b < nblk - 1) {
            prefix[b] = prev + s_total;
            __threadfence();
            ready[b] = 1;
        }
    }
    __syncthreads();

    int base = s_prev;
    if (idx < n) {
        int p = base + incl - v;
        rowptr[idx] = p;
        fill[idx] = p;
    }
    if (b == nblk - 1 && t == SCAN_B - 1) rowptr[n] = base + s_total;
}

// ---------------- CSR fill (re-decodes edge_index) ----------------
__global__ void fill_csr(const void* __restrict__ ei, const float* __restrict__ dinv,
                         int* __restrict__ fill, int2* __restrict__ csr_sn,
                         int nE, int n) {
    int e = blockIdx.x * blockDim.x + threadIdx.x;
    if (e >= nE) return;
    const int* w = (const int*)ei;
    bool is64 = (w[1] == 0) & (w[3] == 0) & (w[5] == 0) & (w[7] == 0);
    int s, d;
    if (is64) {
        s = (int)((const long long*)ei)[e];
        d = (int)((const long long*)ei)[nE + e];
    } else {
        s = w[e];
        d = w[nE + e];
    }
    s = min(max(s, 0), n - 1);
    d = min(max(d, 0), n - 1);
    int pos = atomicAdd(&fill[d], 1);
    float nm = dinv[s] * dinv[d];
    csr_sn[pos] = make_int2(s, __float_as_int(nm));
}

// ---------------- GEMM: Hh[n,128] = X @ W1 (fp32 math, fp16 store) ----------------
__global__ void gemm128(const float* __restrict__ X, const float* __restrict__ W,
                        __half* __restrict__ Hh, int n) {
    __shared__ float xsT[128 * 66];
    int warp = threadIdx.x >> 5;
    int lane = threadIdx.x & 31;
    int rowBase = blockIdx.x * 64;
    int nrows = n - rowBase; if (nrows > 64) nrows = 64;

    int kl = threadIdx.x & 127;
    int rr = threadIdx.x >> 7;
    for (int r = rr; r < nrows; r += 2)
        xsT[kl * 66 + r] = X[(size_t)(rowBase + r) * 128 + kl];
    __syncthreads();

    unsigned long long acc[4][4];
#pragma unroll
    for (int p = 0; p < 4; p++)
#pragma unroll
        for (int c = 0; c < 4; c++) acc[p][c] = 0ull;

    int r0 = warp * 8;
    const float4* Wp = (const float4*)W;
#pragma unroll 4
    for (int k = 0; k < 128; k++) {
        float4 wv = __ldg(Wp + k * 32 + lane);
        unsigned long long wx = dup_f32x2(wv.x);
        unsigned long long wy = dup_f32x2(wv.y);
        unsigned long long wz = dup_f32x2(wv.z);
        unsigned long long ww = dup_f32x2(wv.w);
        const float* base = &xsT[k * 66 + r0];
#pragma unroll
        for (int p = 0; p < 4; p++) {
            unsigned long long xp = *(const unsigned long long*)(base + 2 * p);
            ffma2(acc[p][0], xp, wx);
            ffma2(acc[p][1], xp, wy);
            ffma2(acc[p][2], xp, wz);
            ffma2(acc[p][3], xp, ww);
        }
    }

    uint2* H8 = (uint2*)Hh;   // row = 32 uint2 (128 halves)
#pragma unroll
    for (int p = 0; p < 4; p++) {
        float lo0, hi0, lo1, hi1, lo2, hi2, lo3, hi3;
        unpack2(acc[p][0], lo0, hi0);
        unpack2(acc[p][1], lo1, hi1);
        unpack2(acc[p][2], lo2, hi2);
        unpack2(acc[p][3], lo3, hi3);
        int row0 = rowBase + r0 + 2 * p;
        if (row0 < n) {
            H4U pk;
            pk.h[0] = __floats2half2_rn(lo0, lo1);
            pk.h[1] = __floats2half2_rn(lo2, lo3);
            H8[(size_t)row0 * 32 + lane] = pk.u;
        }
        if (row0 + 1 < n) {
            H4U pk;
            pk.h[0] = __floats2half2_rn(hi0, hi1);
            pk.h[1] = __floats2half2_rn(hi2, hi3);
            H8[(size_t)(row0 + 1) * 32 + lane] = pk.u;
        }
    }
}

// ---------------- GEMM: Hh[n,64] = X2h(fp16) @ W2 (fp32 math, fp16 store) ----------------
__global__ void gemm64(const __half* __restrict__ Xh, const float* __restrict__ W,
                       __half* __restrict__ Hh, int n) {
    __shared__ float xsT[128 * 66];
    int warp = threadIdx.x >> 5;
    int lane = threadIdx.x & 31;
    int rowBase = blockIdx.x * 64;
    int nrows = n - rowBase; if (nrows > 64) nrows = 64;

    int kl = threadIdx.x & 127;
    int rr = threadIdx.x >> 7;
    for (int r = rr; r < nrows; r += 2)
        xsT[kl * 66 + r] = __half2float(__ldg(Xh + (size_t)(rowBase + r) * 128 + kl));
    __syncthreads();

    unsigned long long acc[4][2];
#pragma unroll
    for (int p = 0; p < 4; p++) { acc[p][0] = 0ull; acc[p][1] = 0ull; }

    int r0 = warp * 8;
    const float2* Wp = (const float2*)W;
#pragma unroll 4
    for (int k = 0; k < 128; k++) {
        float2 wv = __ldg(Wp + k * 32 + lane);
        unsigned long long wx = dup_f32x2(wv.x);
        unsigned long long wy = dup_f32x2(wv.y);
        const float* base = &xsT[k * 66 + r0];
#pragma unroll
        for (int p = 0; p < 4; p++) {
            unsigned long long xp = *(const unsigned long long*)(base + 2 * p);
            ffma2(acc[p][0], xp, wx);
            ffma2(acc[p][1], xp, wy);
        }
    }

    __half2* H2h = (__half2*)Hh;   // row = 32 half2
#pragma unroll
    for (int p = 0; p < 4; p++) {
        float lo0, hi0, lo1, hi1;
        unpack2(acc[p][0], lo0, hi0);
        unpack2(acc[p][1], lo1, hi1);
        int row0 = rowBase + r0 + 2 * p;
        if (row0 < n)
            H2h[(size_t)row0 * 32 + lane] = __floats2half2_rn(lo0, lo1);
        if (row0 + 1 < n)
            H2h[(size_t)(row0 + 1) * 32 + lane] = __floats2half2_rn(hi0, hi1);
    }
}

// ---------------- aggregate layer 1: warp/node, 2 edges per warp (half-warp split) ----------------
// lanes 0-15: edge e; lanes 16-31: edge e+1. Each lane: uint4 = 8 halves = channels 8l..8l+7.
__global__ void aggregate128(const __half* __restrict__ Hh, const int* __restrict__ rowptr,
                             const int2* __restrict__ csr_sn,
                             const float* __restrict__ dinv, const float* __restrict__ bias,
                             __half* __restrict__ outh, int n) {
    int node = blockIdx.x * (blockDim.x >> 5) + (threadIdx.x >> 5);
    if (node >= n) return;
    int lane = threadIdx.x & 31;
    int half = lane >> 4;
    int l = lane & 15;
    int beg = rowptr[node], end = rowptr[node + 1];

    const uint4* H16 = (const uint4*)Hh;   // row = 16 uint4 (128 halves)
    float acc[8];
#pragma unroll
    for (int i = 0; i < 8; i++) acc[i] = 0.f;

    int e0 = beg;
    for (; e0 + 4 <= end; e0 += 4) {
        int ea = e0 + half, eb = e0 + 2 + half;
        int2 aa = __ldg(csr_sn + ea);
        int2 ab = __ldg(csr_sn + eb);
        H8U ua, ub;
        ua.u = __ldg(H16 + (size_t)aa.x * 16 + l);
        ub.u = __ldg(H16 + (size_t)ab.x * 16 + l);
        float wa = __int_as_float(aa.y), wb = __int_as_float(ab.y);
#pragma unroll
        for (int i = 0; i < 4; i++) {
            float2 fa = __half22float2(ua.h[i]);
            float2 fb = __half22float2(ub.h[i]);
            acc[2*i]   += fa.x * wa + fb.x * wb;
            acc[2*i+1] += fa.y * wa + fb.y * wb;
        }
    }
    for (; e0 < end; e0 += 2) {
        int e2 = e0 + half;
        bool valid = e2 < end;
        int2 a = valid ? __ldg(csr_sn + e2) : make_int2(0, 0);
        float w = __int_as_float(a.y);   // 0.0f when invalid
        H8U u;
        u.u = __ldg(H16 + (size_t)a.x * 16 + l);
#pragma unroll
        for (int i = 0; i < 4; i++) {
            float2 f = __half22float2(u.h[i]);
            acc[2*i]   += f.x * w;
            acc[2*i+1] += f.y * w;
        }
    }

    // combine half-warps
#pragma unroll
    for (int i = 0; i < 8; i++)
        acc[i] += __shfl_down_sync(0xffffffff, acc[i], 16);

    if (half == 0) {
        float di = dinv[node];
        float selfw = di * di;
        H8U su; su.u = __ldg(H16 + (size_t)node * 16 + l);
        const float4* b4 = (const float4*)bias;
        float4 b0 = b4[2 * l], b1 = b4[2 * l + 1];
        float r[8];
#pragma unroll
        for (int i = 0; i < 4; i++) {
            float2 f = __half22float2(su.h[i]);
            r[2*i]   = acc[2*i]   + f.x * selfw;
            r[2*i+1] = acc[2*i+1] + f.y * selfw;
        }
        r[0] = fmaxf(r[0] + b0.x, 0.f);
        r[1] = fmaxf(r[1] + b0.y, 0.f);
        r[2] = fmaxf(r[2] + b0.z, 0.f);
        r[3] = fmaxf(r[3] + b0.w, 0.f);
        r[4] = fmaxf(r[4] + b1.x, 0.f);
        r[5] = fmaxf(r[5] + b1.y, 0.f);
        r[6] = fmaxf(r[6] + b1.z, 0.f);
        r[7] = fmaxf(r[7] + b1.w, 0.f);
        H8U o;
        o.h[0] = __floats2half2_rn(r[0], r[1]);
        o.h[1] = __floats2half2_rn(r[2], r[3]);
        o.h[2] = __floats2half2_rn(r[4], r[5]);
        o.h[3] = __floats2half2_rn(r[6], r[7]);
        ((uint4*)outh)[(size_t)node * 16 + l] = o.u;
    }
}

// ---------------- aggregate layer 2: warp/node, 2 edges per warp ----------------
// lanes 0-15: edge e; lanes 16-31: edge e+1. Each lane: uint2 = 4 halves = channels 4l..4l+3.
__global__ void aggregate64(const __half* __restrict__ Hh, const int* __restrict__ rowptr,
                            const int2* __restrict__ csr_sn,
                            const float* __restrict__ dinv, const float* __restrict__ bias,
                            float* __restrict__ out, int n) {
    int node = blockIdx.x * (blockDim.x >> 5) + (threadIdx.x >> 5);
    if (node >= n) return;
    int lane = threadIdx.x & 31;
    int half = lane >> 4;
    int l = lane & 15;
    int beg = rowptr[node], end = rowptr[node + 1];

    const uint2* H8 = (const uint2*)Hh;   // row = 16 uint2 (64 halves)
    float acc[4];
#pragma unroll
    for (int i = 0; i < 4; i++) acc[i] = 0.f;

    int e0 = beg;
    for (; e0 + 4 <= end; e0 += 4) {
        int ea = e0 + half, eb = e0 + 2 + half;
        int2 aa = __ldg(csr_sn + ea);
        int2 ab = __ldg(csr_sn + eb);
        H4U ua, ub;
        ua.u = __ldg(H8 + (size_t)aa.x * 16 + l);
        ub.u = __ldg(H8 + (size_t)ab.x * 16 + l);
        float wa = __int_as_float(aa.y), wb = __int_as_float(ab.y);
#pragma unroll
        for (int i = 0; i < 2; i++) {
            float2 fa = __half22float2(ua.h[i]);
            float2 fb = __half22float2(ub.h[i]);
            acc[2*i]   += fa.x * wa + fb.x * wb;
            acc[2*i+1] += fa.y * wa + fb.y * wb;
        }
    }
    for (; e0 < end; e0 += 2) {
        int e2 = e0 + half;
        bool valid = e2 < end;
        int2 a = valid ? __ldg(csr_sn + e2) : make_int2(0, 0);
        float w = __int_as_float(a.y);
        H4U u;
        u.u = __ldg(H8 + (size_t)a.x * 16 + l);
#pragma unroll
        for (int i = 0; i < 2; i++) {
            float2 f = __half22float2(u.h[i]);
            acc[2*i]   += f.x * w;
            acc[2*i+1] += f.y * w;
        }
    }

#pragma unroll
    for (int i = 0; i < 4; i++)
        acc[i] += __shfl_down_sync(0xffffffff, acc[i], 16);

    if (half == 0) {
        float di = dinv[node];
        float selfw = di * di;
        H4U su; su.u = __ldg(H8 + (size_t)node * 16 + l);
        float2 f0 = __half22float2(su.h[0]);
        float2 f1 = __half22float2(su.h[1]);
        float4 b = ((const float4*)bias)[l];
        float4 r;
        r.x = acc[0] + f0.x * selfw + b.x;
        r.y = acc[1] + f0.y * selfw + b.y;
        r.z = acc[2] + f1.x * selfw + b.z;
        r.w = acc[3] + f1.y * selfw + b.w;
        ((float4*)out)[(size_t)node * 16 + l] = r;
    }
}

// ---------------- launch ----------------
extern "C" void kernel_launch(void* const* d_in, const int* in_sizes, int n_in,
                              void* d_out, int out_size) {
    const float* x  = (const float*)d_in[0];
    const void*  ei = d_in[1];
    const float* W1 = (const float*)d_in[2];
    const float* b1 = (const float*)d_in[3];
    const float* W2 = (const float*)d_in[4];
    const float* b2 = (const float*)d_in[5];
    float* out = (float*)d_out;

    int n  = in_sizes[0] / 128;   // 50000
    int nE = in_sizes[1] / 2;     // 800000

    int *p_hist, *p_rowptr, *p_fill, *p_prefix, *p_ready;
    int2* p_csr_sn;
    float *p_dinv;
    __half *p_h1h, *p_x2h, *p_h2h;
    cudaGetSymbolAddress((void**)&p_hist,   g_hist);
    cudaGetSymbolAddress((void**)&p_rowptr, g_rowptr);
    cudaGetSymbolAddress((void**)&p_fill,   g_fill);
    cudaGetSymbolAddress((void**)&p_prefix, g_prefix);
    cudaGetSymbolAddress((void**)&p_ready,  g_ready);
    cudaGetSymbolAddress((void**)&p_dinv,   g_dinv);
    cudaGetSymbolAddress((void**)&p_csr_sn, g_csr_sn);
    cudaGetSymbolAddress((void**)&p_h1h,    g_h1h);
    cudaGetSymbolAddress((void**)&p_x2h,    g_x2h);
    cudaGetSymbolAddress((void**)&p_h2h,    g_h2h);

    const int T = 256;
    int nblk = (n + SCAN_B - 1) / SCAN_B;
    cudaStream_t s2 = g_ss.s;

    // fork: prep chain on side stream, gemm128 on main stream
    cudaEventRecord(g_ss.evFork, 0);
    cudaStreamWaitEvent(s2, g_ss.evFork, 0);

    prep_edges<<<(nE + T - 1) / T, T, 0, s2>>>(ei, p_hist, nE, n);
    scan_chain<<<nblk, SCAN_B, 0, s2>>>(p_hist, p_rowptr, p_fill, p_dinv,
                                        p_prefix, p_ready, n, nblk);
    fill_csr<<<(nE + T - 1) / T, T, 0, s2>>>(ei, p_dinv, p_fill, p_csr_sn, nE, n);
    cudaEventRecord(g_ss.evJoin, s2);

    gemm128<<<(n + 63) / 64, T>>>(x, W1, p_h1h, n);   // concurrent with prep

    // join
    cudaStreamWaitEvent(0, g_ss.evJoin, 0);

    aggregate128<<<(n + 7) / 8, T>>>(p_h1h, p_rowptr, p_csr_sn, p_dinv, b1, p_x2h, n);
    gemm64<<<(n + 63) / 64, T>>>(p_x2h, W2, p_h2h, n);
    aggregate64<<<(n + 7) / 8, T>>>(p_h2h, p_rowptr, p_csr_sn, p_dinv, b2, out, n);
}

// round 12
// speedup vs baseline: 1.5242x; 1.5242x over previous
#include <cuda_runtime.h>
#include <cuda_fp16.h>
#include <mma.h>
#include <cstdint>

using namespace nvcuda;

#define NN 50000
#define EE 800000
#define SCAN_B 1024
#define NBLK ((NN + SCAN_B - 1) / SCAN_B)   // 49

// ---------------- scratch ----------------
__device__ __align__(16) int    g_hist[NN];
__device__ __align__(16) int    g_rowptr[NN + 1];
__device__ __align__(16) int    g_fill[NN];
__device__ __align__(16) int    g_blocksum[NBLK];
__device__ __align__(16) int    g_blockoff[NBLK];
__device__ __align__(16) float  g_dinv[NN];
__device__ __align__(16) int    g_src[EE];
__device__ __align__(16) int    g_dst[EE];
__device__ __align__(16) int2   g_csr_sn[EE];              // {src, norm bits}
__device__ __align__(16) __half g_w1h[128 * 128];
__device__ __align__(16) __half g_w2h[128 * 64];
__device__ __align__(16) __half g_h1h[(size_t)NN * 128];   // fp16 layer-1 linear out
__device__ __align__(16) float  g_x2[(size_t)NN * 128];    // relu(layer1), fp32
__device__ __align__(16) __half g_h2h[(size_t)NN * 64];    // fp16 layer-2 linear out

// ---------------- side stream + events (static init) ----------------
struct SideStream {
    cudaStream_t s;
    cudaEvent_t evFork, evJoin;
    SideStream() {
        cudaStreamCreateWithFlags(&s, cudaStreamNonBlocking);
        cudaEventCreateWithFlags(&evFork, cudaEventDisableTiming);
        cudaEventCreateWithFlags(&evJoin, cudaEventDisableTiming);
    }
};
static SideStream g_ss;

union H4U { uint2 u; __half2 h[2]; };

// ---------------- edge decode (inline dtype detect) + degree histogram ----------------
__global__ void prep_edges(const void* __restrict__ ei,
                           int* __restrict__ src, int* __restrict__ dst,
                           int* __restrict__ hist, int nE, int n) {
    int e = blockIdx.x * blockDim.x + threadIdx.x;
    if (e >= nE) return;
    const int* w = (const int*)ei;
    bool is64 = (w[1] == 0) & (w[3] == 0) & (w[5] == 0) & (w[7] == 0);
    int s, d;
    if (is64) {
        s = (int)((const long long*)ei)[e];
        d = (int)((const long long*)ei)[nE + e];
    } else {
        s = w[e];
        d = w[nE + e];
    }
    s = min(max(s, 0), n - 1);
    d = min(max(d, 0), n - 1);
    src[e] = s;
    dst[e] = d;
    atomicAdd(&hist[d], 1);
}

// ---------------- phase 1: per-block exclusive scan (+dinv) ----------------
__global__ void block_scan(const int* __restrict__ hist, int* __restrict__ rowptr,
                           int* __restrict__ blocksum, float* __restrict__ dinv, int n) {
    __shared__ int warpsum[32];
    int t = threadIdx.x, lane = t & 31, wid = t >> 5;
    int idx = blockIdx.x * SCAN_B + t;
    int v = (idx < n) ? hist[idx] : 0;
    if (idx < n) dinv[idx] = rsqrtf(1.0f + (float)v);
    int x = v;
#pragma unroll
    for (int off = 1; off < 32; off <<= 1) {
        int y = __shfl_up_sync(0xffffffff, x, off);
        if (lane >= off) x += y;
    }
    if (lane == 31) warpsum[wid] = x;
    __syncthreads();
    if (wid == 0) {
        int s = warpsum[lane];
#pragma unroll
        for (int off = 1; off < 32; off <<= 1) {
            int y = __shfl_up_sync(0xffffffff, s, off);
            if (lane >= off) s += y;
        }
        warpsum[lane] = s;
    }
    __syncthreads();
    int warpoff = (wid > 0) ? warpsum[wid - 1] : 0;
    int excl = x + warpoff - v;
    if (idx < n) rowptr[idx] = excl;
    if (t == SCAN_B - 1) blocksum[blockIdx.x] = x + warpoff;
}

// ---------------- phase 2: scan block sums ----------------
__global__ void scan_sums(const int* __restrict__ blocksum, int* __restrict__ blockoff,
                          int* __restrict__ rowptr, int n, int nblk) {
    __shared__ int warpsum[32];
    int t = threadIdx.x, lane = t & 31, wid = t >> 5;
    int v = (t < nblk) ? blocksum[t] : 0;
    int x = v;
#pragma unroll
    for (int off = 1; off < 32; off <<= 1) {
        int y = __shfl_up_sync(0xffffffff, x, off);
        if (lane >= off) x += y;
    }
    if (lane == 31) warpsum[wid] = x;
    __syncthreads();
    if (wid == 0) {
        int s = warpsum[lane];
#pragma unroll
        for (int off = 1; off < 32; off <<= 1) {
            int y = __shfl_up_sync(0xffffffff, s, off);
            if (lane >= off) s += y;
        }
        warpsum[lane] = s;
    }
    __syncthreads();
    int warpoff = (wid > 0) ? warpsum[wid - 1] : 0;
    if (t < nblk) blockoff[t] = x + warpoff - v;
    if (t == nblk - 1) rowptr[n] = x + warpoff;
}

// ---------------- phase 3: add offsets ----------------
__global__ void add_offsets(int* __restrict__ rowptr, int* __restrict__ fill,
                            const int* __restrict__ blockoff, int n) {
    int idx = blockIdx.x * SCAN_B + threadIdx.x;
    if (idx >= n) return;
    int p = rowptr[idx] + blockoff[blockIdx.x];
    rowptr[idx] = p;
    fill[idx] = p;
}

// ---------------- CSR fill ----------------
__global__ void fill_csr(const int* __restrict__ src, const int* __restrict__ dst,
                         const float* __restrict__ dinv, int* __restrict__ fill,
                         int2* __restrict__ csr_sn, int nE) {
    int e = blockIdx.x * blockDim.x + threadIdx.x;
    if (e >= nE) return;
    int s = src[e], d = dst[e];
    int pos = atomicAdd(&fill[d], 1);
    float nm = dinv[s] * dinv[d];
    csr_sn[pos] = make_int2(s, __float_as_int(nm));
}

// ---------------- weight conversion fp32 -> fp16 ----------------
__global__ void convert_w(const float* __restrict__ W1, const float* __restrict__ W2,
                          __half* __restrict__ W1h, __half* __restrict__ W2h) {
    int i = blockIdx.x * blockDim.x + threadIdx.x;
    if (i < 128 * 128 / 2) {
        float2 f = ((const float2*)W1)[i];
        ((__half2*)W1h)[i] = __floats2half2_rn(f.x, f.y);
    }
    if (i < 128 * 64 / 2) {
        float2 f = ((const float2*)W2)[i];
        ((__half2*)W2h)[i] = __floats2half2_rn(f.x, f.y);
    }
}

// ---------------- WMMA GEMM: Hh[n,128] = X[n,128](->fp16) @ W1h[128,128] ----------------
// 256 thr = 8 warps; block tile 64x128. Warp (strip=w/2, colHalf=w&1): 16 rows x 64 cols.
__global__ void gemm128_wmma(const float* __restrict__ X, const __half* __restrict__ Wh,
                             __half* __restrict__ Hh, int n) {
    __shared__ __align__(16) char smbuf[64 * 132 * 4];   // 33792 B
    __half* As = (__half*)smbuf;     // pitch 136 halves
    float*  Cs = (float*)smbuf;      // pitch 132 floats
    int tid = threadIdx.x;
    int warp = tid >> 5;
    int rowBase = blockIdx.x * 64;

    // load A tile: fp32 -> fp16 smem
    for (int idx = tid; idx < 64 * 32; idx += 256) {   // float4 units
        int r = idx >> 5, c4 = idx & 31;
        int row = rowBase + r;
        float4 v = (row < n) ? ((const float4*)(X + (size_t)row * 128))[c4]
                             : make_float4(0.f, 0.f, 0.f, 0.f);
        __half2* dst = (__half2*)(As + r * 136 + c4 * 4);
        dst[0] = __floats2half2_rn(v.x, v.y);
        dst[1] = __floats2half2_rn(v.z, v.w);
    }
    __syncthreads();

    int strip = warp >> 1;
    int colHalf = warp & 1;
    wmma::fragment<wmma::accumulator, 16, 16, 16, float> c[4];
#pragma unroll
    for (int i = 0; i < 4; i++) wmma::fill_fragment(c[i], 0.f);

#pragma unroll
    for (int k16 = 0; k16 < 8; k16++) {
        wmma::fragment<wmma::matrix_a, 16, 16, 16, __half, wmma::row_major> a;
        wmma::load_matrix_sync(a, As + strip * 16 * 136 + k16 * 16, 136);
#pragma unroll
        for (int i = 0; i < 4; i++) {
            wmma::fragment<wmma::matrix_b, 16, 16, 16, __half, wmma::row_major> b;
            int ncol = colHalf * 64 + i * 16;
            wmma::load_matrix_sync(b, Wh + k16 * 16 * 128 + ncol, 128);
            wmma::mma_sync(c[i], a, b, c[i]);
        }
    }
    __syncthreads();   // done reading As

#pragma unroll
    for (int i = 0; i < 4; i++) {
        int ncol = colHalf * 64 + i * 16;
        wmma::store_matrix_sync(Cs + strip * 16 * 132 + ncol, c[i], 132, wmma::mem_row_major);
    }
    __syncthreads();

    __half2* H2 = (__half2*)Hh;   // row = 64 half2
    for (int idx = tid; idx < 64 * 64; idx += 256) {
        int r = idx >> 6, c2 = idx & 63;
        int row = rowBase + r;
        if (row < n) {
            float2 f = ((const float2*)(Cs + r * 132))[c2];
            H2[(size_t)row * 64 + c2] = __floats2half2_rn(f.x, f.y);
        }
    }
}

// ---------------- WMMA GEMM: Hh[n,64] = X2[n,128](->fp16) @ W2h[128,64] ----------------
// Warp (strip=w/2, colPair=w&1): 16 rows x 32 cols (2 tiles).
__global__ void gemm64_wmma(const float* __restrict__ X, const __half* __restrict__ Wh,
                            __half* __restrict__ Hh, int n) {
    __shared__ __align__(16) char smbuf[64 * 136 * 2];   // 17408 B
    __half* As = (__half*)smbuf;     // pitch 136 halves
    float*  Cs = (float*)smbuf;      // pitch 68 floats (64*68*4 = 17408)
    int tid = threadIdx.x;
    int warp = tid >> 5;
    int rowBase = blockIdx.x * 64;

    for (int idx = tid; idx < 64 * 32; idx += 256) {
        int r = idx >> 5, c4 = idx & 31;
        int row = rowBase + r;
        float4 v = (row < n) ? ((const float4*)(X + (size_t)row * 128))[c4]
                             : make_float4(0.f, 0.f, 0.f, 0.f);
        __half2* dst = (__half2*)(As + r * 136 + c4 * 4);
        dst[0] = __floats2half2_rn(v.x, v.y);
        dst[1] = __floats2half2_rn(v.z, v.w);
    }
    __syncthreads();

    int strip = warp >> 1;
    int colPair = warp & 1;
    wmma::fragment<wmma::accumulator, 16, 16, 16, float> c[2];
#pragma unroll
    for (int i = 0; i < 2; i++) wmma::fill_fragment(c[i], 0.f);

#pragma unroll
    for (int k16 = 0; k16 < 8; k16++) {
        wmma::fragment<wmma::matrix_a, 16, 16, 16, __half, wmma::row_major> a;
        wmma::load_matrix_sync(a, As + strip * 16 * 136 + k16 * 16, 136);
#pragma unroll
        for (int i = 0; i < 2; i++) {
            wmma::fragment<wmma::matrix_b, 16, 16, 16, __half, wmma::row_major> b;
            int ncol = colPair * 32 + i * 16;
            wmma::load_matrix_sync(b, Wh + k16 * 16 * 64 + ncol, 64);
            wmma::mma_sync(c[i], a, b, c[i]);
        }
    }
    __syncthreads();

#pragma unroll
    for (int i = 0; i < 2; i++) {
        int ncol = colPair * 32 + i * 16;
        wmma::store_matrix_sync(Cs + strip * 16 * 68 + ncol, c[i], 68, wmma::mem_row_major);
    }
    __syncthreads();

    __half2* H2 = (__half2*)Hh;   // row = 32 half2
    for (int idx = tid; idx < 64 * 32; idx += 256) {
        int r = idx >> 5, c2 = idx & 31;
        int row = rowBase + r;
        if (row < n) {
            float2 f = ((const float2*)(Cs + r * 68))[c2];
            H2[(size_t)row * 32 + c2] = __floats2half2_rn(f.x, f.y);
        }
    }
}

// ---------------- aggregate layer 1 (r10): fp16 gather, fp32 accum, fused self+bias+relu ----------------
__global__ void aggregate128(const __half* __restrict__ Hh, const int* __restrict__ rowptr,
                             const int2* __restrict__ csr_sn,
                             const float* __restrict__ dinv, const float* __restrict__ bias,
                             float* __restrict__ out, int n) {
    int node = blockIdx.x * (blockDim.x >> 5) + (threadIdx.x >> 5);
    if (node >= n) return;
    int lane = threadIdx.x & 31;
    int beg = rowptr[node], end = rowptr[node + 1];
    float di = dinv[node];
    float selfw = di * di;  // 1/deg

    const uint2* H8 = (const uint2*)Hh;
    H4U sf; sf.u = __ldg(H8 + (size_t)node * 32 + lane);
    float2 s0 = __half22float2(sf.h[0]);
    float2 s1 = __half22float2(sf.h[1]);
    float4 acc = make_float4(s0.x * selfw, s0.y * selfw, s1.x * selfw, s1.y * selfw);

    int e = beg;
    for (; e + 4 <= end; e += 4) {
        int2 a0 = __ldg(csr_sn + e + 0);
        int2 a1 = __ldg(csr_sn + e + 1);
        int2 a2 = __ldg(csr_sn + e + 2);
        int2 a3 = __ldg(csr_sn + e + 3);
        H4U u0, u1, u2, u3;
        u0.u = __ldg(H8 + (size_t)a0.x * 32 + lane);
        u1.u = __ldg(H8 + (size_t)a1.x * 32 + lane);
        u2.u = __ldg(H8 + (size_t)a2.x * 32 + lane);
        u3.u = __ldg(H8 + (size_t)a3.x * 32 + lane);
        float w0 = __int_as_float(a0.y), w1 = __int_as_float(a1.y);
        float w2 = __int_as_float(a2.y), w3 = __int_as_float(a3.y);
        float2 f;
        f = __half22float2(u0.h[0]); acc.x += f.x * w0; acc.y += f.y * w0;
        f = __half22float2(u0.h[1]); acc.z += f.x * w0; acc.w += f.y * w0;
        f = __half22float2(u1.h[0]); acc.x += f.x * w1; acc.y += f.y * w1;
        f = __half22float2(u1.h[1]); acc.z += f.x * w1; acc.w += f.y * w1;
        f = __half22float2(u2.h[0]); acc.x += f.x * w2; acc.y += f.y * w2;
        f = __half22float2(u2.h[1]); acc.z += f.x * w2; acc.w += f.y * w2;
        f = __half22float2(u3.h[0]); acc.x += f.x * w3; acc.y += f.y * w3;
        f = __half22float2(u3.h[1]); acc.z += f.x * w3; acc.w += f.y * w3;
    }
    for (; e < end; e++) {
        int2 a = __ldg(csr_sn + e);
        float w = __int_as_float(a.y);
        H4U u; u.u = __ldg(H8 + (size_t)a.x * 32 + lane);
        float2 f;
        f = __half22float2(u.h[0]); acc.x += f.x * w; acc.y += f.y * w;
        f = __half22float2(u.h[1]); acc.z += f.x * w; acc.w += f.y * w;
    }
    float4 b = ((const float4*)bias)[lane];
    acc.x = fmaxf(acc.x + b.x, 0.f);
    acc.y = fmaxf(acc.y + b.y, 0.f);
    acc.z = fmaxf(acc.z + b.z, 0.f);
    acc.w = fmaxf(acc.w + b.w, 0.f);
    ((float4*)out)[(size_t)node * 32 + lane] = acc;
}

// ---------------- aggregate layer 2 (r10): fp16 gather, fp32 accum, fused ----------------
__global__ void aggregate64(const __half* __restrict__ Hh, const int* __restrict__ rowptr,
                            const int2* __restrict__ csr_sn,
                            const float* __restrict__ dinv, const float* __restrict__ bias,
                            float* __restrict__ out, int n) {
    int node = blockIdx.x * (blockDim.x >> 5) + (threadIdx.x >> 5);
    if (node >= n) return;
    int lane = threadIdx.x & 31;
    int beg = rowptr[node], end = rowptr[node + 1];
    float di = dinv[node];
    float selfw = di * di;

    const __half2* H2h = (const __half2*)Hh;
    float2 sf = __half22float2(__ldg(H2h + (size_t)node * 32 + lane));
    float2 acc = make_float2(sf.x * selfw, sf.y * selfw);

    int e = beg;
    for (; e + 4 <= end; e += 4) {
        int2 a0 = __ldg(csr_sn + e + 0);
        int2 a1 = __ldg(csr_sn + e + 1);
        int2 a2 = __ldg(csr_sn + e + 2);
        int2 a3 = __ldg(csr_sn + e + 3);
        float2 v0 = __half22float2(__ldg(H2h + (size_t)a0.x * 32 + lane));
        float2 v1 = __half22float2(__ldg(H2h + (size_t)a1.x * 32 + lane));
        float2 v2 = __half22float2(__ldg(H2h + (size_t)a2.x * 32 + lane));
        float2 v3 = __half22float2(__ldg(H2h + (size_t)a3.x * 32 + lane));
        float w0 = __int_as_float(a0.y), w1 = __int_as_float(a1.y);
        float w2 = __int_as_float(a2.y), w3 = __int_as_float(a3.y);
        acc.x += v0.x * w0; acc.y += v0.y * w0;
        acc.x += v1.x * w1; acc.y += v1.y * w1;
        acc.x += v2.x * w2; acc.y += v2.y * w2;
        acc.x += v3.x * w3; acc.y += v3.y * w3;
    }
    for (; e < end; e++) {
        int2 a = __ldg(csr_sn + e);
        float w = __int_as_float(a.y);
        float2 v = __half22float2(__ldg(H2h + (size_t)a.x * 32 + lane));
        acc.x += v.x * w; acc.y += v.y * w;
    }
    float2 b = ((const float2*)bias)[lane];
    acc.x += b.x;
    acc.y += b.y;
    ((float2*)out)[(size_t)node * 32 + lane] = acc;
}

// ---------------- launch ----------------
extern "C" void kernel_launch(void* const* d_in, const int* in_sizes, int n_in,
                              void* d_out, int out_size) {
    const float* x  = (const float*)d_in[0];
    const void*  ei = d_in[1];
    const float* W1 = (const float*)d_in[2];
    const float* b1 = (const float*)d_in[3];
    const float* W2 = (const float*)d_in[4];
    const float* b2 = (const float*)d_in[5];
    float* out = (float*)d_out;

    int n  = in_sizes[0] / 128;   // 50000
    int nE = in_sizes[1] / 2;     // 800000

    int *p_hist, *p_rowptr, *p_fill, *p_bsum, *p_boff, *p_src, *p_dst;
    int2* p_csr_sn;
    float *p_dinv, *p_x2;
    __half *p_w1h, *p_w2h, *p_h1h, *p_h2h;
    cudaGetSymbolAddress((void**)&p_hist,   g_hist);
    cudaGetSymbolAddress((void**)&p_rowptr, g_rowptr);
    cudaGetSymbolAddress((void**)&p_fill,   g_fill);
    cudaGetSymbolAddress((void**)&p_bsum,   g_blocksum);
    cudaGetSymbolAddress((void**)&p_boff,   g_blockoff);
    cudaGetSymbolAddress((void**)&p_dinv,   g_dinv);
    cudaGetSymbolAddress((void**)&p_src,    g_src);
    cudaGetSymbolAddress((void**)&p_dst,    g_dst);
    cudaGetSymbolAddress((void**)&p_csr_sn, g_csr_sn);
    cudaGetSymbolAddress((void**)&p_w1h,    g_w1h);
    cudaGetSymbolAddress((void**)&p_w2h,    g_w2h);
    cudaGetSymbolAddress((void**)&p_h1h,    g_h1h);
    cudaGetSymbolAddress((void**)&p_x2,     g_x2);
    cudaGetSymbolAddress((void**)&p_h2h,    g_h2h);

    const int T = 256;
    int nblk = (n + SCAN_B - 1) / SCAN_B;
    cudaStream_t s2 = g_ss.s;

    // fork: prep chain on side stream, weight-convert + gemm128 on main stream
    cudaEventRecord(g_ss.evFork, 0);
    cudaStreamWaitEvent(s2, g_ss.evFork, 0);

    cudaMemsetAsync(p_hist, 0, (size_t)n * sizeof(int), s2);
    prep_edges<<<(nE + T - 1) / T, T, 0, s2>>>(ei, p_src, p_dst, p_hist, nE, n);
    block_scan<<<nblk, SCAN_B, 0, s2>>>(p_hist, p_rowptr, p_bsum, p_dinv, n);
    scan_sums<<<1, SCAN_B, 0, s2>>>(p_bsum, p_boff, p_rowptr, n, nblk);
    add_offsets<<<nblk, SCAN_B, 0, s2>>>(p_rowptr, p_fill, p_boff, n);
    fill_csr<<<(nE + T - 1) / T, T, 0, s2>>>(p_src, p_dst, p_dinv, p_fill, p_csr_sn, nE);
    cudaEventRecord(g_ss.evJoin, s2);

    convert_w<<<32, T>>>(W1, W2, p_w1h, p_w2h);
    gemm128_wmma<<<(n + 63) / 64, T>>>(x, p_w1h, p_h1h, n);   // concurrent with prep

    // join
    cudaStreamWaitEvent(0, g_ss.evJoin, 0);

    aggregate128<<<(n + 7) / 8, T>>>(p_h1h, p_rowptr, p_csr_sn, p_dinv, b1, p_x2, n);
    gemm64_wmma<<<(n + 63) / 64, T>>>(p_x2, p_w2h, p_h2h, n);
    aggregate64<<<(n + 7) / 8, T>>>(p_h2h, p_rowptr, p_csr_sn, p_dinv, b2, out, n);
}

// round 13
// speedup vs baseline: 1.5292x; 1.0033x over previous
#include <cuda_runtime.h>
#include <cuda_fp16.h>
#include <mma.h>
#include <cstdint>

using namespace nvcuda;

#define NN 50000
#define EE 800000
#define SCAN_B 1024
#define NBLK ((NN + SCAN_B - 1) / SCAN_B)   // 49

// ---------------- scratch ----------------
__device__ __align__(16) int    g_hist[NN];        // zero at load; self-zeroing each run
__device__ __align__(16) int    g_rowptr[NN + 1];
__device__ __align__(16) int    g_fill[NN];
__device__ __align__(16) int    g_blocksum[NBLK];
__device__ __align__(16) float  g_dinv[NN];
__device__ __align__(16) int    g_src[EE];
__device__ __align__(16) int    g_dst[EE];
__device__ __align__(16) int2   g_csr_sn[EE];              // {src, norm bits}
__device__ __align__(16) __half g_w1h[128 * 128];
__device__ __align__(16) __half g_w2h[128 * 64];
__device__ __align__(16) __half g_h1h[(size_t)NN * 128];   // fp16 layer-1 linear out
__device__ __align__(16) float  g_x2[(size_t)NN * 128];    // relu(layer1), fp32
__device__ __align__(16) __half g_h2h[(size_t)NN * 64];    // fp16 layer-2 linear out

// ---------------- side stream + events (static init) ----------------
struct SideStream {
    cudaStream_t s;
    cudaEvent_t evFork, evJoin;
    SideStream() {
        cudaStreamCreateWithFlags(&s, cudaStreamNonBlocking);
        cudaEventCreateWithFlags(&evFork, cudaEventDisableTiming);
        cudaEventCreateWithFlags(&evJoin, cudaEventDisableTiming);
    }
};
static SideStream g_ss;

union H4U { uint2 u; __half2 h[2]; };

// ---------------- edge decode (inline dtype detect) + degree histogram ----------------
__global__ void prep_edges(const void* __restrict__ ei,
                           int* __restrict__ src, int* __restrict__ dst,
                           int* __restrict__ hist, int nE, int n) {
    int e = blockIdx.x * blockDim.x + threadIdx.x;
    if (e >= nE) return;
    const int* w = (const int*)ei;
    bool is64 = (w[1] == 0) & (w[3] == 0) & (w[5] == 0) & (w[7] == 0);
    int s, d;
    if (is64) {
        s = (int)((const long long*)ei)[e];
        d = (int)((const long long*)ei)[nE + e];
    } else {
        s = w[e];
        d = w[nE + e];
    }
    s = min(max(s, 0), n - 1);
    d = min(max(d, 0), n - 1);
    src[e] = s;
    dst[e] = d;
    atomicAdd(&hist[d], 1);
}

// ---------------- scan phase 1: per-block exclusive scan (+dinv, hist self-zero) ----------------
__global__ void block_scan(int* __restrict__ hist, int* __restrict__ rowptr,
                           int* __restrict__ blocksum, float* __restrict__ dinv, int n) {
    __shared__ int warpsum[32];
    int t = threadIdx.x, lane = t & 31, wid = t >> 5;
    int idx = blockIdx.x * SCAN_B + t;
    int v = (idx < n) ? hist[idx] : 0;
    if (idx < n) {
        dinv[idx] = rsqrtf(1.0f + (float)v);
        hist[idx] = 0;   // self-zero for next graph replay
    }
    int x = v;
#pragma unroll
    for (int off = 1; off < 32; off <<= 1) {
        int y = __shfl_up_sync(0xffffffff, x, off);
        if (lane >= off) x += y;
    }
    if (lane == 31) warpsum[wid] = x;
    __syncthreads();
    if (wid == 0) {
        int s = warpsum[lane];
#pragma unroll
        for (int off = 1; off < 32; off <<= 1) {
            int y = __shfl_up_sync(0xffffffff, s, off);
            if (lane >= off) s += y;
        }
        warpsum[lane] = s;
    }
    __syncthreads();
    int warpoff = (wid > 0) ? warpsum[wid - 1] : 0;
    int excl = x + warpoff - v;
    if (idx < n) rowptr[idx] = excl;
    if (t == SCAN_B - 1) blocksum[blockIdx.x] = x + warpoff;
}

// ---------------- scan phase 2 (merged): each block scans blocksums + applies offset ----------------
__global__ void finalize_scan(const int* __restrict__ blocksum, int* __restrict__ rowptr,
                              int* __restrict__ fill, int n, int nblk) {
    __shared__ int s_off;
    int b = blockIdx.x;
    int t = threadIdx.x;
    if (t < 32) {
        int acc = 0;
        for (int i = t; i < b; i += 32) acc += blocksum[i];   // b <= 48: one iter per lane
#pragma unroll
        for (int off = 16; off; off >>= 1) acc += __shfl_down_sync(0xffffffff, acc, off);
        if (t == 0) s_off = acc;
    }
    __syncthreads();
    int off = s_off;
    int idx = b * SCAN_B + t;
    if (idx < n) {
        int p = rowptr[idx] + off;
        rowptr[idx] = p;
        fill[idx] = p;
    }
    if (b == nblk - 1 && t == 0) rowptr[n] = off + blocksum[nblk - 1];
}

// ---------------- CSR fill ----------------
__global__ void fill_csr(const int* __restrict__ src, const int* __restrict__ dst,
                         const float* __restrict__ dinv, int* __restrict__ fill,
                         int2* __restrict__ csr_sn, int nE) {
    int e = blockIdx.x * blockDim.x + threadIdx.x;
    if (e >= nE) return;
    int s = src[e], d = dst[e];
    int pos = atomicAdd(&fill[d], 1);
    float nm = dinv[s] * dinv[d];
    csr_sn[pos] = make_int2(s, __float_as_int(nm));
}

// ---------------- weight conversion fp32 -> fp16 ----------------
__global__ void convert_w(const float* __restrict__ W1, const float* __restrict__ W2,
                          __half* __restrict__ W1h, __half* __restrict__ W2h) {
    int i = blockIdx.x * blockDim.x + threadIdx.x;
    if (i < 128 * 128 / 2) {
        float2 f = ((const float2*)W1)[i];
        ((__half2*)W1h)[i] = __floats2half2_rn(f.x, f.y);
    }
    if (i < 128 * 64 / 2) {
        float2 f = ((const float2*)W2)[i];
        ((__half2*)W2h)[i] = __floats2half2_rn(f.x, f.y);
    }
}

// ---------------- WMMA GEMM: Hh[n,128] = X[n,128](->fp16) @ W1h[128,128] ----------------
__global__ void gemm128_wmma(const float* __restrict__ X, const __half* __restrict__ Wh,
                             __half* __restrict__ Hh, int n) {
    __shared__ __align__(16) char smbuf[64 * 132 * 4];   // 33792 B
    __half* As = (__half*)smbuf;     // pitch 136 halves
    float*  Cs = (float*)smbuf;      // pitch 132 floats
    int tid = threadIdx.x;
    int warp = tid >> 5;
    int rowBase = blockIdx.x * 64;

    for (int idx = tid; idx < 64 * 32; idx += 256) {   // float4 units
        int r = idx >> 5, c4 = idx & 31;
        int row = rowBase + r;
        float4 v = (row < n) ? ((const float4*)(X + (size_t)row * 128))[c4]
                             : make_float4(0.f, 0.f, 0.f, 0.f);
        __half2* dst = (__half2*)(As + r * 136 + c4 * 4);
        dst[0] = __floats2half2_rn(v.x, v.y);
        dst[1] = __floats2half2_rn(v.z, v.w);
    }
    __syncthreads();

    int strip = warp >> 1;
    int colHalf = warp & 1;
    wmma::fragment<wmma::accumulator, 16, 16, 16, float> c[4];
#pragma unroll
    for (int i = 0; i < 4; i++) wmma::fill_fragment(c[i], 0.f);

#pragma unroll
    for (int k16 = 0; k16 < 8; k16++) {
        wmma::fragment<wmma::matrix_a, 16, 16, 16, __half, wmma::row_major> a;
        wmma::load_matrix_sync(a, As + strip * 16 * 136 + k16 * 16, 136);
#pragma unroll
        for (int i = 0; i < 4; i++) {
            wmma::fragment<wmma::matrix_b, 16, 16, 16, __half, wmma::row_major> b;
            int ncol = colHalf * 64 + i * 16;
            wmma::load_matrix_sync(b, Wh + k16 * 16 * 128 + ncol, 128);
            wmma::mma_sync(c[i], a, b, c[i]);
        }
    }
    __syncthreads();

#pragma unroll
    for (int i = 0; i < 4; i++) {
        int ncol = colHalf * 64 + i * 16;
        wmma::store_matrix_sync(Cs + strip * 16 * 132 + ncol, c[i], 132, wmma::mem_row_major);
    }
    __syncthreads();

    __half2* H2 = (__half2*)Hh;   // row = 64 half2
    for (int idx = tid; idx < 64 * 64; idx += 256) {
        int r = idx >> 6, c2 = idx & 63;
        int row = rowBase + r;
        if (row < n) {
            float2 f = ((const float2*)(Cs + r * 132))[c2];
            H2[(size_t)row * 64 + c2] = __floats2half2_rn(f.x, f.y);
        }
    }
}

// ---------------- WMMA GEMM: Hh[n,64] = X2[n,128](->fp16) @ W2h[128,64] ----------------
__global__ void gemm64_wmma(const float* __restrict__ X, const __half* __restrict__ Wh,
                            __half* __restrict__ Hh, int n) {
    __shared__ __align__(16) char smbuf[64 * 136 * 2];   // 17408 B
    __half* As = (__half*)smbuf;     // pitch 136 halves
    float*  Cs = (float*)smbuf;      // pitch 68 floats
    int tid = threadIdx.x;
    int warp = tid >> 5;
    int rowBase = blockIdx.x * 64;

    for (int idx = tid; idx < 64 * 32; idx += 256) {
        int r = idx >> 5, c4 = idx & 31;
        int row = rowBase + r;
        float4 v = (row < n) ? ((const float4*)(X + (size_t)row * 128))[c4]
                             : make_float4(0.f, 0.f, 0.f, 0.f);
        __half2* dst = (__half2*)(As + r * 136 + c4 * 4);
        dst[0] = __floats2half2_rn(v.x, v.y);
        dst[1] = __floats2half2_rn(v.z, v.w);
    }
    __syncthreads();

    int strip = warp >> 1;
    int colPair = warp & 1;
    wmma::fragment<wmma::accumulator, 16, 16, 16, float> c[2];
#pragma unroll
    for (int i = 0; i < 2; i++) wmma::fill_fragment(c[i], 0.f);

#pragma unroll
    for (int k16 = 0; k16 < 8; k16++) {
        wmma::fragment<wmma::matrix_a, 16, 16, 16, __half, wmma::row_major> a;
        wmma::load_matrix_sync(a, As + strip * 16 * 136 + k16 * 16, 136);
#pragma unroll
        for (int i = 0; i < 2; i++) {
            wmma::fragment<wmma::matrix_b, 16, 16, 16, __half, wmma::row_major> b;
            int ncol = colPair * 32 + i * 16;
            wmma::load_matrix_sync(b, Wh + k16 * 16 * 64 + ncol, 64);
            wmma::mma_sync(c[i], a, b, c[i]);
        }
    }
    __syncthreads();

#pragma unroll
    for (int i = 0; i < 2; i++) {
        int ncol = colPair * 32 + i * 16;
        wmma::store_matrix_sync(Cs + strip * 16 * 68 + ncol, c[i], 68, wmma::mem_row_major);
    }
    __syncthreads();

    __half2* H2 = (__half2*)Hh;   // row = 32 half2
    for (int idx = tid; idx < 64 * 32; idx += 256) {
        int r = idx >> 5, c2 = idx & 31;
        int row = rowBase + r;
        if (row < n) {
            float2 f = ((const float2*)(Cs + r * 68))[c2];
            H2[(size_t)row * 32 + c2] = __floats2half2_rn(f.x, f.y);
        }
    }
}

// ---------------- aggregate layer 1: fp16 gather, fp32 accum, fused self+bias+relu ----------------
__global__ void aggregate128(const __half* __restrict__ Hh, const int* __restrict__ rowptr,
                             const int2* __restrict__ csr_sn,
                             const float* __restrict__ dinv, const float* __restrict__ bias,
                             float* __restrict__ out, int n) {
    int node = blockIdx.x * (blockDim.x >> 5) + (threadIdx.x >> 5);
    if (node >= n) return;
    int lane = threadIdx.x & 31;
    int beg = rowptr[node], end = rowptr[node + 1];
    float di = dinv[node];
    float selfw = di * di;  // 1/deg

    const uint2* H8 = (const uint2*)Hh;
    H4U sf; sf.u = __ldg(H8 + (size_t)node * 32 + lane);
    float2 s0 = __half22float2(sf.h[0]);
    float2 s1 = __half22float2(sf.h[1]);
    float4 acc = make_float4(s0.x * selfw, s0.y * selfw, s1.x * selfw, s1.y * selfw);

    int e = beg;
    for (; e + 4 <= end; e += 4) {
        int2 a0 = __ldg(csr_sn + e + 0);
        int2 a1 = __ldg(csr_sn + e + 1);
        int2 a2 = __ldg(csr_sn + e + 2);
        int2 a3 = __ldg(csr_sn + e + 3);
        H4U u0, u1, u2, u3;
        u0.u = __ldg(H8 + (size_t)a0.x * 32 + lane);
        u1.u = __ldg(H8 + (size_t)a1.x * 32 + lane);
        u2.u = __ldg(H8 + (size_t)a2.x * 32 + lane);
        u3.u = __ldg(H8 + (size_t)a3.x * 32 + lane);
        float w0 = __int_as_float(a0.y), w1 = __int_as_float(a1.y);
        float w2 = __int_as_float(a2.y), w3 = __int_as_float(a3.y);
        float2 f;
        f = __half22float2(u0.h[0]); acc.x += f.x * w0; acc.y += f.y * w0;
        f = __half22float2(u0.h[1]); acc.z += f.x * w0; acc.w += f.y * w0;
        f = __half22float2(u1.h[0]); acc.x += f.x * w1; acc.y += f.y * w1;
        f = __half22float2(u1.h[1]); acc.z += f.x * w1; acc.w += f.y * w1;
        f = __half22float2(u2.h[0]); acc.x += f.x * w2; acc.y += f.y * w2;
        f = __half22float2(u2.h[1]); acc.z += f.x * w2; acc.w += f.y * w2;
        f = __half22float2(u3.h[0]); acc.x += f.x * w3; acc.y += f.y * w3;
        f = __half22float2(u3.h[1]); acc.z += f.x * w3; acc.w += f.y * w3;
    }
    for (; e < end; e++) {
        int2 a = __ldg(csr_sn + e);
        float w = __int_as_float(a.y);
        H4U u; u.u = __ldg(H8 + (size_t)a.x * 32 + lane);
        float2 f;
        f = __half22float2(u.h[0]); acc.x += f.x * w; acc.y += f.y * w;
        f = __half22float2(u.h[1]); acc.z += f.x * w; acc.w += f.y * w;
    }
    float4 b = ((const float4*)bias)[lane];
    acc.x = fmaxf(acc.x + b.x, 0.f);
    acc.y = fmaxf(acc.y + b.y, 0.f);
    acc.z = fmaxf(acc.z + b.z, 0.f);
    acc.w = fmaxf(acc.w + b.w, 0.f);
    ((float4*)out)[(size_t)node * 32 + lane] = acc;
}

// ---------------- aggregate layer 2: fp16 gather, fp32 accum, fused ----------------
__global__ void aggregate64(const __half* __restrict__ Hh, const int* __restrict__ rowptr,
                            const int2* __restrict__ csr_sn,
                            const float* __restrict__ dinv, const float* __restrict__ bias,
                            float* __restrict__ out, int n) {
    int node = blockIdx.x * (blockDim.x >> 5) + (threadIdx.x >> 5);
    if (node >= n) return;
    int lane = threadIdx.x & 31;
    int beg = rowptr[node], end = rowptr[node + 1];
    float di = dinv[node];
    float selfw = di * di;

    const __half2* H2h = (const __half2*)Hh;
    float2 sf = __half22float2(__ldg(H2h + (size_t)node * 32 + lane));
    float2 acc = make_float2(sf.x * selfw, sf.y * selfw);

    int e = beg;
    for (; e + 4 <= end; e += 4) {
        int2 a0 = __ldg(csr_sn + e + 0);
        int2 a1 = __ldg(csr_sn + e + 1);
        int2 a2 = __ldg(csr_sn + e + 2);
        int2 a3 = __ldg(csr_sn + e + 3);
        float2 v0 = __half22float2(__ldg(H2h + (size_t)a0.x * 32 + lane));
        float2 v1 = __half22float2(__ldg(H2h + (size_t)a1.x * 32 + lane));
        float2 v2 = __half22float2(__ldg(H2h + (size_t)a2.x * 32 + lane));
        float2 v3 = __half22float2(__ldg(H2h + (size_t)a3.x * 32 + lane));
        float w0 = __int_as_float(a0.y), w1 = __int_as_float(a1.y);
        float w2 = __int_as_float(a2.y), w3 = __int_as_float(a3.y);
        acc.x += v0.x * w0; acc.y += v0.y * w0;
        acc.x += v1.x * w1; acc.y += v1.y * w1;
        acc.x += v2.x * w2; acc.y += v2.y * w2;
        acc.x += v3.x * w3; acc.y += v3.y * w3;
    }
    for (; e < end; e++) {
        int2 a = __ldg(csr_sn + e);
        float w = __int_as_float(a.y);
        float2 v = __half22float2(__ldg(H2h + (size_t)a.x * 32 + lane));
        acc.x += v.x * w; acc.y += v.y * w;
    }
    float2 b = ((const float2*)bias)[lane];
    acc.x += b.x;
    acc.y += b.y;
    ((float2*)out)[(size_t)node * 32 + lane] = acc;
}

// ---------------- launch ----------------
extern "C" void kernel_launch(void* const* d_in, const int* in_sizes, int n_in,
                              void* d_out, int out_size) {
    const float* x  = (const float*)d_in[0];
    const void*  ei = d_in[1];
    const float* W1 = (const float*)d_in[2];
    const float* b1 = (const float*)d_in[3];
    const float* W2 = (const float*)d_in[4];
    const float* b2 = (const float*)d_in[5];
    float* out = (float*)d_out;

    int n  = in_sizes[0] / 128;   // 50000
    int nE = in_sizes[1] / 2;     // 800000

    int *p_hist, *p_rowptr, *p_fill, *p_bsum, *p_src, *p_dst;
    int2* p_csr_sn;
    float *p_dinv, *p_x2;
    __half *p_w1h, *p_w2h, *p_h1h, *p_h2h;
    cudaGetSymbolAddress((void**)&p_hist,   g_hist);
    cudaGetSymbolAddress((void**)&p_rowptr, g_rowptr);
    cudaGetSymbolAddress((void**)&p_fill,   g_fill);
    cudaGetSymbolAddress((void**)&p_bsum,   g_blocksum);
    cudaGetSymbolAddress((void**)&p_dinv,   g_dinv);
    cudaGetSymbolAddress((void**)&p_src,    g_src);
    cudaGetSymbolAddress((void**)&p_dst,    g_dst);
    cudaGetSymbolAddress((void**)&p_csr_sn, g_csr_sn);
    cudaGetSymbolAddress((void**)&p_w1h,    g_w1h);
    cudaGetSymbolAddress((void**)&p_w2h,    g_w2h);
    cudaGetSymbolAddress((void**)&p_h1h,    g_h1h);
    cudaGetSymbolAddress((void**)&p_x2,     g_x2);
    cudaGetSymbolAddress((void**)&p_h2h,    g_h2h);

    const int T = 256;
    int nblk = (n + SCAN_B - 1) / SCAN_B;
    cudaStream_t s2 = g_ss.s;

    // fork: prep chain on side stream, weight-convert + gemm128 on main stream
    cudaEventRecord(g_ss.evFork, 0);
    cudaStreamWaitEvent(s2, g_ss.evFork, 0);

    prep_edges<<<(nE + T - 1) / T, T, 0, s2>>>(ei, p_src, p_dst, p_hist, nE, n);
    block_scan<<<nblk, SCAN_B, 0, s2>>>(p_hist, p_rowptr, p_bsum, p_dinv, n);
    finalize_scan<<<nblk, SCAN_B, 0, s2>>>(p_bsum, p_rowptr, p_fill, n, nblk);
    fill_csr<<<(nE + T - 1) / T, T, 0, s2>>>(p_src, p_dst, p_dinv, p_fill, p_csr_sn, nE);
    cudaEventRecord(g_ss.evJoin, s2);

    convert_w<<<32, T>>>(W1, W2, p_w1h, p_w2h);
    gemm128_wmma<<<(n + 63) / 64, T>>>(x, p_w1h, p_h1h, n);   // concurrent with prep

    // join
    cudaStreamWaitEvent(0, g_ss.evJoin, 0);

    aggregate128<<<(n + 7) / 8, T>>>(p_h1h, p_rowptr, p_csr_sn, p_dinv, b1, p_x2, n);
    gemm64_wmma<<<(n + 63) / 64, T>>>(p_x2, p_w2h, p_h2h, n);
    aggregate64<<<(n + 7) / 8, T>>>(p_h2h, p_rowptr, p_csr_sn, p_dinv, b2, out, n);
}

// round 14
// speedup vs baseline: 1.5836x; 1.0355x over previous
#include <cuda_runtime.h>
#include <cuda_fp16.h>
#include <mma.h>
#include <cstdint>

using namespace nvcuda;

#define NN 50000
#define EE 800000
#define SCAN_B 1024
#define NBLK ((NN + SCAN_B - 1) / SCAN_B)   // 49

// ---------------- scratch ----------------
__device__ __align__(16) int    g_hist[NN];        // zero at load; self-zeroing each run
__device__ __align__(16) int    g_rowptr[NN + 1];
__device__ __align__(16) int    g_fill[NN];
__device__ __align__(16) int    g_blocksum[NBLK];
__device__ __align__(16) float  g_dinv[NN];
__device__ __align__(16) int    g_src[EE];
__device__ __align__(16) int    g_dst[EE];
__device__ __align__(16) int2   g_csr_sn[EE];              // {src, norm bits}
__device__ __align__(16) __half g_w1h[128 * 128];
__device__ __align__(16) __half g_w2h[128 * 64];
__device__ __align__(16) __half g_h1h[(size_t)NN * 128];   // fp16 layer-1 linear out
__device__ __align__(16) __half g_h2h[(size_t)NN * 64];    // fp16 layer-2 linear out

// ---------------- side stream + events (static init) ----------------
struct SideStream {
    cudaStream_t s;
    cudaEvent_t evFork, evJoin;
    SideStream() {
        cudaStreamCreateWithFlags(&s, cudaStreamNonBlocking);
        cudaEventCreateWithFlags(&evFork, cudaEventDisableTiming);
        cudaEventCreateWithFlags(&evJoin, cudaEventDisableTiming);
    }
};
static SideStream g_ss;

union H4U { uint2 u; __half2 h[2]; };

// ---------------- edge decode (inline dtype detect) + degree histogram ----------------
__global__ void prep_edges(const void* __restrict__ ei,
                           int* __restrict__ src, int* __restrict__ dst,
                           int* __restrict__ hist, int nE, int n) {
    int e = blockIdx.x * blockDim.x + threadIdx.x;
    if (e >= nE) return;
    const int* w = (const int*)ei;
    bool is64 = (w[1] == 0) & (w[3] == 0) & (w[5] == 0) & (w[7] == 0);
    int s, d;
    if (is64) {
        s = (int)((const long long*)ei)[e];
        d = (int)((const long long*)ei)[nE + e];
    } else {
        s = w[e];
        d = w[nE + e];
    }
    s = min(max(s, 0), n - 1);
    d = min(max(d, 0), n - 1);
    src[e] = s;
    dst[e] = d;
    atomicAdd(&hist[d], 1);
}

// ---------------- scan phase 1: per-block exclusive scan (+dinv, hist self-zero) ----------------
__global__ void block_scan(int* __restrict__ hist, int* __restrict__ rowptr,
                           int* __restrict__ blocksum, float* __restrict__ dinv, int n) {
    __shared__ int warpsum[32];
    int t = threadIdx.x, lane = t & 31, wid = t >> 5;
    int idx = blockIdx.x * SCAN_B + t;
    int v = (idx < n) ? hist[idx] : 0;
    if (idx < n) {
        dinv[idx] = rsqrtf(1.0f + (float)v);
        hist[idx] = 0;   // self-zero for next graph replay
    }
    int x = v;
#pragma unroll
    for (int off = 1; off < 32; off <<= 1) {
        int y = __shfl_up_sync(0xffffffff, x, off);
        if (lane >= off) x += y;
    }
    if (lane == 31) warpsum[wid] = x;
    __syncthreads();
    if (wid == 0) {
        int s = warpsum[lane];
#pragma unroll
        for (int off = 1; off < 32; off <<= 1) {
            int y = __shfl_up_sync(0xffffffff, s, off);
            if (lane >= off) s += y;
        }
        warpsum[lane] = s;
    }
    __syncthreads();
    int warpoff = (wid > 0) ? warpsum[wid - 1] : 0;
    int excl = x + warpoff - v;
    if (idx < n) rowptr[idx] = excl;
    if (t == SCAN_B - 1) blocksum[blockIdx.x] = x + warpoff;
}

// ---------------- scan phase 2 (merged): each block scans blocksums + applies offset ----------------
__global__ void finalize_scan(const int* __restrict__ blocksum, int* __restrict__ rowptr,
                              int* __restrict__ fill, int n, int nblk) {
    __shared__ int s_off;
    int b = blockIdx.x;
    int t = threadIdx.x;
    if (t < 32) {
        int acc = 0;
        for (int i = t; i < b; i += 32) acc += blocksum[i];
#pragma unroll
        for (int off = 16; off; off >>= 1) acc += __shfl_down_sync(0xffffffff, acc, off);
        if (t == 0) s_off = acc;
    }
    __syncthreads();
    int off = s_off;
    int idx = b * SCAN_B + t;
    if (idx < n) {
        int p = rowptr[idx] + off;
        rowptr[idx] = p;
        fill[idx] = p;
    }
    if (b == nblk - 1 && t == 0) rowptr[n] = off + blocksum[nblk - 1];
}

// ---------------- CSR fill ----------------
__global__ void fill_csr(const int* __restrict__ src, const int* __restrict__ dst,
                         const float* __restrict__ dinv, int* __restrict__ fill,
                         int2* __restrict__ csr_sn, int nE) {
    int e = blockIdx.x * blockDim.x + threadIdx.x;
    if (e >= nE) return;
    int s = src[e], d = dst[e];
    int pos = atomicAdd(&fill[d], 1);
    float nm = dinv[s] * dinv[d];
    csr_sn[pos] = make_int2(s, __float_as_int(nm));
}

// ---------------- weight conversion fp32 -> fp16 ----------------
__global__ void convert_w(const float* __restrict__ W1, const float* __restrict__ W2,
                          __half* __restrict__ W1h, __half* __restrict__ W2h) {
    int i = blockIdx.x * blockDim.x + threadIdx.x;
    if (i < 128 * 128 / 2) {
        float2 f = ((const float2*)W1)[i];
        ((__half2*)W1h)[i] = __floats2half2_rn(f.x, f.y);
    }
    if (i < 128 * 64 / 2) {
        float2 f = ((const float2*)W2)[i];
        ((__half2*)W2h)[i] = __floats2half2_rn(f.x, f.y);
    }
}

// ---------------- WMMA GEMM: Hh[n,128] = X[n,128](->fp16) @ W1h[128,128] ----------------
__global__ void gemm128_wmma(const float* __restrict__ X, const __half* __restrict__ Wh,
                             __half* __restrict__ Hh, int n) {
    __shared__ __align__(16) char smbuf[64 * 132 * 4];   // 33792 B
    __half* As = (__half*)smbuf;     // pitch 136 halves
    float*  Cs = (float*)smbuf;      // pitch 132 floats
    int tid = threadIdx.x;
    int warp = tid >> 5;
    int rowBase = blockIdx.x * 64;

    for (int idx = tid; idx < 64 * 32; idx += 256) {   // float4 units
        int r = idx >> 5, c4 = idx & 31;
        int row = rowBase + r;
        float4 v = (row < n) ? ((const float4*)(X + (size_t)row * 128))[c4]
                             : make_float4(0.f, 0.f, 0.f, 0.f);
        __half2* dst = (__half2*)(As + r * 136 + c4 * 4);
        dst[0] = __floats2half2_rn(v.x, v.y);
        dst[1] = __floats2half2_rn(v.z, v.w);
    }
    __syncthreads();

    int strip = warp >> 1;
    int colHalf = warp & 1;
    wmma::fragment<wmma::accumulator, 16, 16, 16, float> c[4];
#pragma unroll
    for (int i = 0; i < 4; i++) wmma::fill_fragment(c[i], 0.f);

#pragma unroll
    for (int k16 = 0; k16 < 8; k16++) {
        wmma::fragment<wmma::matrix_a, 16, 16, 16, __half, wmma::row_major> a;
        wmma::load_matrix_sync(a, As + strip * 16 * 136 + k16 * 16, 136);
#pragma unroll
        for (int i = 0; i < 4; i++) {
            wmma::fragment<wmma::matrix_b, 16, 16, 16, __half, wmma::row_major> b;
            int ncol = colHalf * 64 + i * 16;
            wmma::load_matrix_sync(b, Wh + k16 * 16 * 128 + ncol, 128);
            wmma::mma_sync(c[i], a, b, c[i]);
        }
    }
    __syncthreads();

#pragma unroll
    for (int i = 0; i < 4; i++) {
        int ncol = colHalf * 64 + i * 16;
        wmma::store_matrix_sync(Cs + strip * 16 * 132 + ncol, c[i], 132, wmma::mem_row_major);
    }
    __syncthreads();

    __half2* H2 = (__half2*)Hh;   // row = 64 half2
    for (int idx = tid; idx < 64 * 64; idx += 256) {
        int r = idx >> 6, c2 = idx & 63;
        int row = rowBase + r;
        if (row < n) {
            float2 f = ((const float2*)(Cs + r * 132))[c2];
            H2[(size_t)row * 64 + c2] = __floats2half2_rn(f.x, f.y);
        }
    }
}

// ---------------- FUSED: aggregate layer1 (gather+self+bias+relu, fp16 into smem tile)
//                  + WMMA gemm64 (tile @ W2h -> h2h) ----------------
// Block: 256 thr = 8 warps, 64 nodes. Phase 1: warp w aggregates nodes w*8..w*8+7,
// writing fp16 rows into As (pitch 136). Phase 2: gemm64 WMMA on As.
__global__ void agg_gemm64_fused(const __half* __restrict__ Hh, const int* __restrict__ rowptr,
                                 const int2* __restrict__ csr_sn,
                                 const float* __restrict__ dinv, const float* __restrict__ bias,
                                 const __half* __restrict__ Wh, __half* __restrict__ Hout, int n) {
    __shared__ __align__(16) char smbuf[64 * 136 * 2];   // 17408 B
    __half* As = (__half*)smbuf;     // pitch 136 halves
    float*  Cs = (float*)smbuf;      // pitch 68 floats
    int tid = threadIdx.x;
    int warp = tid >> 5;
    int lane = tid & 31;
    int rowBase = blockIdx.x * 64;

    // ---- phase 1: aggregate 8 nodes per warp ----
    const uint2* H8 = (const uint2*)Hh;
    float4 b4 = ((const float4*)bias)[lane];   // lane's 4 channels
#pragma unroll 1
    for (int i = 0; i < 8; i++) {
        int r = warp * 8 + i;
        int node = rowBase + r;
        float4 acc;
        if (node < n) {
            int beg = rowptr[node], end = rowptr[node + 1];
            float di = dinv[node];
            float selfw = di * di;

            H4U sf; sf.u = __ldg(H8 + (size_t)node * 32 + lane);
            float2 s0 = __half22float2(sf.h[0]);
            float2 s1 = __half22float2(sf.h[1]);
            acc = make_float4(s0.x * selfw, s0.y * selfw, s1.x * selfw, s1.y * selfw);

            int e = beg;
            for (; e + 4 <= end; e += 4) {
                int2 a0 = __ldg(csr_sn + e + 0);
                int2 a1 = __ldg(csr_sn + e + 1);
                int2 a2 = __ldg(csr_sn + e + 2);
                int2 a3 = __ldg(csr_sn + e + 3);
                H4U u0, u1, u2, u3;
                u0.u = __ldg(H8 + (size_t)a0.x * 32 + lane);
                u1.u = __ldg(H8 + (size_t)a1.x * 32 + lane);
                u2.u = __ldg(H8 + (size_t)a2.x * 32 + lane);
                u3.u = __ldg(H8 + (size_t)a3.x * 32 + lane);
                float w0 = __int_as_float(a0.y), w1 = __int_as_float(a1.y);
                float w2 = __int_as_float(a2.y), w3 = __int_as_float(a3.y);
                float2 f;
                f = __half22float2(u0.h[0]); acc.x += f.x * w0; acc.y += f.y * w0;
                f = __half22float2(u0.h[1]); acc.z += f.x * w0; acc.w += f.y * w0;
                f = __half22float2(u1.h[0]); acc.x += f.x * w1; acc.y += f.y * w1;
                f = __half22float2(u1.h[1]); acc.z += f.x * w1; acc.w += f.y * w1;
                f = __half22float2(u2.h[0]); acc.x += f.x * w2; acc.y += f.y * w2;
                f = __half22float2(u2.h[1]); acc.z += f.x * w2; acc.w += f.y * w2;
                f = __half22float2(u3.h[0]); acc.x += f.x * w3; acc.y += f.y * w3;
                f = __half22float2(u3.h[1]); acc.z += f.x * w3; acc.w += f.y * w3;
            }
            for (; e < end; e++) {
                int2 a = __ldg(csr_sn + e);
                float w = __int_as_float(a.y);
                H4U u; u.u = __ldg(H8 + (size_t)a.x * 32 + lane);
                float2 f;
                f = __half22float2(u.h[0]); acc.x += f.x * w; acc.y += f.y * w;
                f = __half22float2(u.h[1]); acc.z += f.x * w; acc.w += f.y * w;
            }
            acc.x = fmaxf(acc.x + b4.x, 0.f);
            acc.y = fmaxf(acc.y + b4.y, 0.f);
            acc.z = fmaxf(acc.z + b4.z, 0.f);
            acc.w = fmaxf(acc.w + b4.w, 0.f);
        } else {
            acc = make_float4(0.f, 0.f, 0.f, 0.f);
        }
        // fp16 row into WMMA A tile: lane's 4 channels at col lane*4
        H4U pk;
        pk.h[0] = __floats2half2_rn(acc.x, acc.y);
        pk.h[1] = __floats2half2_rn(acc.z, acc.w);
        *(uint2*)(As + r * 136 + lane * 4) = pk.u;
    }
    __syncthreads();

    // ---- phase 2: WMMA 64x64x128 on As @ Wh ----
    int strip = warp >> 1;
    int colPair = warp & 1;
    wmma::fragment<wmma::accumulator, 16, 16, 16, float> c[2];
#pragma unroll
    for (int i = 0; i < 2; i++) wmma::fill_fragment(c[i], 0.f);

#pragma unroll
    for (int k16 = 0; k16 < 8; k16++) {
        wmma::fragment<wmma::matrix_a, 16, 16, 16, __half, wmma::row_major> a;
        wmma::load_matrix_sync(a, As + strip * 16 * 136 + k16 * 16, 136);
#pragma unroll
        for (int i = 0; i < 2; i++) {
            wmma::fragment<wmma::matrix_b, 16, 16, 16, __half, wmma::row_major> b;
            int ncol = colPair * 32 + i * 16;
            wmma::load_matrix_sync(b, Wh + k16 * 16 * 64 + ncol, 64);
            wmma::mma_sync(c[i], a, b, c[i]);
        }
    }
    __syncthreads();

#pragma unroll
    for (int i = 0; i < 2; i++) {
        int ncol = colPair * 32 + i * 16;
        wmma::store_matrix_sync(Cs + strip * 16 * 68 + ncol, c[i], 68, wmma::mem_row_major);
    }
    __syncthreads();

    __half2* H2 = (__half2*)Hout;   // row = 32 half2
    for (int idx = tid; idx < 64 * 32; idx += 256) {
        int r = idx >> 5, c2 = idx & 31;
        int row = rowBase + r;
        if (row < n) {
            float2 f = ((const float2*)(Cs + r * 68))[c2];
            H2[(size_t)row * 32 + c2] = __floats2half2_rn(f.x, f.y);
        }
    }
}

// ---------------- aggregate layer 2: fp16 gather, fp32 accum, fused ----------------
__global__ void aggregate64(const __half* __restrict__ Hh, const int* __restrict__ rowptr,
                            const int2* __restrict__ csr_sn,
                            const float* __restrict__ dinv, const float* __restrict__ bias,
                            float* __restrict__ out, int n) {
    int node = blockIdx.x * (blockDim.x >> 5) + (threadIdx.x >> 5);
    if (node >= n) return;
    int lane = threadIdx.x & 31;
    int beg = rowptr[node], end = rowptr[node + 1];
    float di = dinv[node];
    float selfw = di * di;

    const __half2* H2h = (const __half2*)Hh;
    float2 sf = __half22float2(__ldg(H2h + (size_t)node * 32 + lane));
    float2 acc = make_float2(sf.x * selfw, sf.y * selfw);

    int e = beg;
    for (; e + 4 <= end; e += 4) {
        int2 a0 = __ldg(csr_sn + e + 0);
        int2 a1 = __ldg(csr_sn + e + 1);
        int2 a2 = __ldg(csr_sn + e + 2);
        int2 a3 = __ldg(csr_sn + e + 3);
        float2 v0 = __half22float2(__ldg(H2h + (size_t)a0.x * 32 + lane));
        float2 v1 = __half22float2(__ldg(H2h + (size_t)a1.x * 32 + lane));
        float2 v2 = __half22float2(__ldg(H2h + (size_t)a2.x * 32 + lane));
        float2 v3 = __half22float2(__ldg(H2h + (size_t)a3.x * 32 + lane));
        float w0 = __int_as_float(a0.y), w1 = __int_as_float(a1.y);
        float w2 = __int_as_float(a2.y), w3 = __int_as_float(a3.y);
        acc.x += v0.x * w0; acc.y += v0.y * w0;
        acc.x += v1.x * w1; acc.y += v1.y * w1;
        acc.x += v2.x * w2; acc.y += v2.y * w2;
        acc.x += v3.x * w3; acc.y += v3.y * w3;
    }
    for (; e < end; e++) {
        int2 a = __ldg(csr_sn + e);
        float w = __int_as_float(a.y);
        float2 v = __half22float2(__ldg(H2h + (size_t)a.x * 32 + lane));
        acc.x += v.x * w; acc.y += v.y * w;
    }
    float2 b = ((const float2*)bias)[lane];
    acc.x += b.x;
    acc.y += b.y;
    ((float2*)out)[(size_t)node * 32 + lane] = acc;
}

// ---------------- launch ----------------
extern "C" void kernel_launch(void* const* d_in, const int* in_sizes, int n_in,
                              void* d_out, int out_size) {
    const float* x  = (const float*)d_in[0];
    const void*  ei = d_in[1];
    const float* W1 = (const float*)d_in[2];
    const float* b1 = (const float*)d_in[3];
    const float* W2 = (const float*)d_in[4];
    const float* b2 = (const float*)d_in[5];
    float* out = (float*)d_out;

    int n  = in_sizes[0] / 128;   // 50000
    int nE = in_sizes[1] / 2;     // 800000

    int *p_hist, *p_rowptr, *p_fill, *p_bsum, *p_src, *p_dst;
    int2* p_csr_sn;
    float *p_dinv;
    __half *p_w1h, *p_w2h, *p_h1h, *p_h2h;
    cudaGetSymbolAddress((void**)&p_hist,   g_hist);
    cudaGetSymbolAddress((void**)&p_rowptr, g_rowptr);
    cudaGetSymbolAddress((void**)&p_fill,   g_fill);
    cudaGetSymbolAddress((void**)&p_bsum,   g_blocksum);
    cudaGetSymbolAddress((void**)&p_dinv,   g_dinv);
    cudaGetSymbolAddress((void**)&p_src,    g_src);
    cudaGetSymbolAddress((void**)&p_dst,    g_dst);
    cudaGetSymbolAddress((void**)&p_csr_sn, g_csr_sn);
    cudaGetSymbolAddress((void**)&p_w1h,    g_w1h);
    cudaGetSymbolAddress((void**)&p_w2h,    g_w2h);
    cudaGetSymbolAddress((void**)&p_h1h,    g_h1h);
    cudaGetSymbolAddress((void**)&p_h2h,    g_h2h);

    const int T = 256;
    int nblk = (n + SCAN_B - 1) / SCAN_B;
    cudaStream_t s2 = g_ss.s;

    // fork: prep chain on side stream, weight-convert + gemm128 on main stream
    cudaEventRecord(g_ss.evFork, 0);
    cudaStreamWaitEvent(s2, g_ss.evFork, 0);

    prep_edges<<<(nE + T - 1) / T, T, 0, s2>>>(ei, p_src, p_dst, p_hist, nE, n);
    block_scan<<<nblk, SCAN_B, 0, s2>>>(p_hist, p_rowptr, p_bsum, p_dinv, n);
    finalize_scan<<<nblk, SCAN_B, 0, s2>>>(p_bsum, p_rowptr, p_fill, n, nblk);
    fill_csr<<<(nE + T - 1) / T, T, 0, s2>>>(p_src, p_dst, p_dinv, p_fill, p_csr_sn, nE);
    cudaEventRecord(g_ss.evJoin, s2);

    convert_w<<<32, T>>>(W1, W2, p_w1h, p_w2h);
    gemm128_wmma<<<(n + 63) / 64, T>>>(x, p_w1h, p_h1h, n);   // concurrent with prep

    // join
    cudaStreamWaitEvent(0, g_ss.evJoin, 0);

    agg_gemm64_fused<<<(n + 63) / 64, T>>>(p_h1h, p_rowptr, p_csr_sn, p_dinv, b1,
                                           p_w2h, p_h2h, n);
    aggregate64<<<(n + 7) / 8, T>>>(p_h2h, p_rowptr, p_csr_sn, p_dinv, b2, out, n);
}